// round 11
// baseline (speedup 1.0000x reference)
#include <cuda_runtime.h>
#include <cuda_fp16.h>

#define NN 100000
#define NE 1250000
#define DD 64
#define NB_SCAN 98   // ceil(NN/1024)
#define ISTR 65      // padded Ism row stride (floats)
#define GROWS 128    // rows per GEMM block
#define GEMM_SMEM ((4096 + GROWS * ISTR) * 4)
#define AGG_BLOCKS 1480

// ---------------- scratch (static device globals; no allocation) ----------------
__device__ int     g_is64;
__device__ int     g_ticket;
__device__ int     g_count[NN];
__device__ int     g_wcount[NN];
__device__ int     g_rowptr[NN];         // block-local exclusive prefix
__device__ int     g_bsum[128];
__device__ int     g_boff[128];          // per-1024-block offsets
__device__ float   g_dinv[NN];
__device__ int2    g_csr[NE];            // {src, weight-as-int}
__device__ __half2 g_hwh[NN * 32];       // h @ W in fp16 (gather table, 128 B/row)
__device__ float   g_agg[NN * DD];       // aggregated (pre-BN), fp32
__device__ float   g_colsum[DD * 32];    // 128B-strided slots
__device__ float   g_colsq[DD * 32];
__device__ float   g_scaleA[DD];
__device__ float   g_shiftB[DD];

// ---------------- f32x2 helpers ----------------
__device__ __forceinline__ unsigned long long ffma2(unsigned long long a,
                                                    unsigned long long b,
                                                    unsigned long long c) {
    unsigned long long d;
    asm("fma.rn.f32x2 %0, %1, %2, %3;" : "=l"(d) : "l"(a), "l"(b), "l"(c));
    return d;
}
__device__ __forceinline__ unsigned long long splat2(float v) {
    unsigned long long o;
    asm("mov.b64 %0, {%1, %1};" : "=l"(o) : "f"(v));
    return o;
}

// ---------------- setup ----------------
__global__ void k_zero_detect(const int* __restrict__ ei) {
    int i = blockIdx.x * blockDim.x + threadIdx.x;
    if (i < NN) { g_count[i] = 0; g_wcount[i] = 0; }
    if (blockIdx.x == 0) {
        if (threadIdx.x < 64) { g_colsum[threadIdx.x * 32] = 0.f; g_colsq[threadIdx.x * 32] = 0.f; }
        __shared__ int cnt;
        if (threadIdx.x == 0) cnt = 0;
        __syncthreads();
        int nz = 0;
#pragma unroll
        for (int j = 0; j < 8; j++) {
            int pos = 2 * (threadIdx.x + j * 256) + 1;
            if (ei[pos] != 0) nz = 1;
        }
        if (nz) atomicAdd(&cnt, 1);
        __syncthreads();
        if (threadIdx.x == 0) g_is64 = (cnt == 0) ? 1 : 0;
    }
}

__device__ __forceinline__ int load_idx(const void* ei, long long pos) {
    if (g_is64) return (int)((const long long*)ei)[pos];
    return ((const int*)ei)[pos];
}

__global__ void k_degree(const void* __restrict__ ei) {
    int t = blockIdx.x * blockDim.x + threadIdx.x;
    int e0 = 2 * t;
    if (e0 >= NE) return;
    int d0, d1 = -1;
    if (g_is64) {
        const longlong2* p = (const longlong2*)((const long long*)ei + NE + e0);
        longlong2 v = (e0 + 1 < NE) ? *p : make_longlong2(((const long long*)ei)[NE + e0], -1);
        d0 = (int)v.x; d1 = (int)v.y;
    } else {
        const int* p = (const int*)ei + NE + e0;
        d0 = p[0]; d1 = (e0 + 1 < NE) ? p[1] : -1;
    }
    if ((unsigned)d0 < NN) atomicAdd(&g_count[d0], 1);
    if ((unsigned)d1 < NN) atomicAdd(&g_count[d1], 1);
}

// block-local scan + dinv; last block (ticket) scans the 98 block sums -> g_boff
__global__ void k_scan1() {
    __shared__ int sm[1024];
    __shared__ int s_last;
    int tid = threadIdx.x;
    int i = blockIdx.x * 1024 + tid;
    int v = (i < NN) ? g_count[i] : 0;
    if (i < NN) g_dinv[i] = rsqrtf((float)(v + 1));  // +1 self loop
    sm[tid] = v;
    for (int off = 1; off < 1024; off <<= 1) {
        __syncthreads();
        int t = (tid >= off) ? sm[tid - off] : 0;
        __syncthreads();
        sm[tid] += t;
    }
    if (i < NN) g_rowptr[i] = sm[tid] - v;
    if (tid == 1023) g_bsum[blockIdx.x] = sm[1023];
    if (tid == 0) {
        __threadfence();
        int t = atomicAdd(&g_ticket, 1);
        s_last = (t == NB_SCAN - 1);
    }
    __syncthreads();
    if (s_last) {
        __threadfence();
        int v2 = (tid < NB_SCAN) ? g_bsum[tid] : 0;
        sm[tid] = (tid < 128) ? v2 : 0;
        for (int off = 1; off < 128; off <<= 1) {
            __syncthreads();
            int t = (tid >= off && tid < 128) ? sm[tid - off] : 0;
            __syncthreads();
            if (tid < 128) sm[tid] += t;
        }
        if (tid < 128) g_boff[tid] = sm[tid] - v2;
        if (tid == 0) g_ticket = 0;
    }
}

__global__ void k_fill(const void* __restrict__ ei) {
    int e = blockIdx.x * blockDim.x + threadIdx.x;
    if (e >= NE) return;
    int s = load_idx(ei, e);
    int d = load_idx(ei, (long long)NE + e);
    if ((unsigned)s >= NN || (unsigned)d >= NN) return;
    float w = g_dinv[s] * g_dinv[d];
    int p = g_rowptr[d] + g_boff[d >> 10] + atomicAdd(&g_wcount[d], 1);
    if ((unsigned)p < NE) g_csr[p] = make_int2(s, __float_as_int(w));
}

// ---------------- per-layer GEMM: hwh = fp16( BN_prev(h) @ W ) ----------------
// 128 rows x 64 cols per block; 256 thr; r4c8 register tile; ~48.5 KB smem -> 3-4 blocks/SM.
__global__ __launch_bounds__(256) void k_gemm(const float* __restrict__ x,
                                              const float* __restrict__ W, int layer) {
    extern __shared__ float smdyn[];
    float* Wsm = smdyn;                 // 64*64
    float* Ism = smdyn + 4096;          // GROWS*ISTR
    __shared__ float As[DD], Bs[DD];
    int tid = threadIdx.x;
    const float* gin = (layer == 0) ? x : g_agg;
    int bn = (layer > 0);
    if (bn && tid < 64) { As[tid] = g_scaleA[tid]; Bs[tid] = g_shiftB[tid]; }
    __syncthreads();

    int row0 = blockIdx.x * GROWS;
#pragma unroll
    for (int i = 0; i < 4; i++) {
        int idx4 = tid + i * 256;
        *(float4*)&Wsm[idx4 * 4] = ((const float4*)W)[idx4];
    }
#pragma unroll
    for (int i = 0; i < 8; i++) {
        int idx4 = tid + i * 256;
        int r = idx4 >> 4, c4 = (idx4 & 15) * 4;
        int gr = row0 + r;
        float4 v = {0.f, 0.f, 0.f, 0.f};
        if (gr < NN) {
            v = *(const float4*)&gin[gr * DD + c4];
            if (bn) {
                v.x = fmaxf(fmaf(v.x, As[c4 + 0], Bs[c4 + 0]), 0.f);
                v.y = fmaxf(fmaf(v.y, As[c4 + 1], Bs[c4 + 1]), 0.f);
                v.z = fmaxf(fmaf(v.z, As[c4 + 2], Bs[c4 + 2]), 0.f);
                v.w = fmaxf(fmaf(v.w, As[c4 + 3], Bs[c4 + 3]), 0.f);
            }
        }
        float* ip = &Ism[r * ISTR + c4];
        ip[0] = v.x; ip[1] = v.y; ip[2] = v.z; ip[3] = v.w;
    }
    __syncthreads();

    int tx = tid & 7, ty = tid >> 3;          // tx: col-group of 8, ty: row-group of 4 (0..31)
    unsigned long long acc[4][4];
#pragma unroll
    for (int r = 0; r < 4; r++)
#pragma unroll
        for (int j = 0; j < 4; j++) acc[r][j] = 0ull;

    const float* irow = &Ism[(ty * 4) * ISTR];
#pragma unroll 8
    for (int k = 0; k < DD; k++) {
        ulonglong2 wA = *(const ulonglong2*)&Wsm[k * DD + tx * 8];
        ulonglong2 wB = *(const ulonglong2*)&Wsm[k * DD + tx * 8 + 4];
#pragma unroll
        for (int r = 0; r < 4; r++) {
            unsigned long long iv = splat2(irow[r * ISTR + k]);
            acc[r][0] = ffma2(iv, wA.x, acc[r][0]);
            acc[r][1] = ffma2(iv, wA.y, acc[r][1]);
            acc[r][2] = ffma2(iv, wB.x, acc[r][2]);
            acc[r][3] = ffma2(iv, wB.y, acc[r][3]);
        }
    }
#pragma unroll
    for (int r = 0; r < 4; r++) {
        int gr = row0 + ty * 4 + r;
        if (gr < NN) {
            float o[8];
#pragma unroll
            for (int j = 0; j < 4; j++)
                asm("mov.b64 {%0, %1}, %2;" : "=f"(o[2 * j]), "=f"(o[2 * j + 1]) : "l"(acc[r][j]));
            __half2 h4[4];
#pragma unroll
            for (int j = 0; j < 4; j++) h4[j] = __floats2half2_rn(o[2 * j], o[2 * j + 1]);
            *(uint2*)&g_hwh[gr * 32 + tx * 4]     = *(uint2*)&h4[0];
            *(uint2*)&g_hwh[gr * 32 + tx * 4 + 2] = *(uint2*)&h4[2];
        }
    }
}

// ---------------- aggregation (1 node/warp, 4-unrolled) + BN stats + finalize ----------------
__device__ __forceinline__ int rp(int n) { return g_rowptr[n] + g_boff[n >> 10]; }

__global__ __launch_bounds__(256) void k_agg(const float* __restrict__ bias,
                                             const float* __restrict__ gamma,
                                             const float* __restrict__ beta) {
    __shared__ float s_sum[8][64];
    __shared__ float s_sq[8][64];
    __shared__ int s_last;
    int lane = threadIdx.x & 31;
    int gw = (blockIdx.x * blockDim.x + threadIdx.x) >> 5;
    int nw = (gridDim.x * 256) >> 5;
    float bx = bias[2 * lane], by = bias[2 * lane + 1];
    float sx = 0.f, sy = 0.f, qx = 0.f, qy = 0.f;
    for (int n = gw; n < NN; n += nw) {
        int p = rp(n);
        int p1 = (n + 1 == NN) ? NE : rp(n + 1);
        float ax = 0.f, ay = 0.f;
#pragma unroll 1
        for (; p + 4 <= p1; p += 4) {
            int2 e0 = g_csr[p];
            int2 e1 = g_csr[p + 1];
            int2 e2 = g_csr[p + 2];
            int2 e3 = g_csr[p + 3];
            float2 v0 = __half22float2(g_hwh[e0.x * 32 + lane]);
            float2 v1 = __half22float2(g_hwh[e1.x * 32 + lane]);
            float2 v2 = __half22float2(g_hwh[e2.x * 32 + lane]);
            float2 v3 = __half22float2(g_hwh[e3.x * 32 + lane]);
            float w0 = __int_as_float(e0.y), w1 = __int_as_float(e1.y);
            float w2 = __int_as_float(e2.y), w3 = __int_as_float(e3.y);
            ax = fmaf(v0.x, w0, ax); ay = fmaf(v0.y, w0, ay);
            ax = fmaf(v1.x, w1, ax); ay = fmaf(v1.y, w1, ay);
            ax = fmaf(v2.x, w2, ax); ay = fmaf(v2.y, w2, ay);
            ax = fmaf(v3.x, w3, ax); ay = fmaf(v3.y, w3, ay);
        }
#pragma unroll 1
        for (; p < p1; p++) {
            int2 e = g_csr[p];
            float w = __int_as_float(e.y);
            float2 v = __half22float2(g_hwh[e.x * 32 + lane]);
            ax = fmaf(v.x, w, ax); ay = fmaf(v.y, w, ay);
        }
        float di = g_dinv[n];
        float sw = di * di;
        float2 sv = __half22float2(g_hwh[n * 32 + lane]);
        ax = fmaf(sv.x, sw, ax) + bx;
        ay = fmaf(sv.y, sw, ay) + by;
        *(float2*)&g_agg[n * DD + 2 * lane] = make_float2(ax, ay);
        sx += ax; sy += ay; qx += ax * ax; qy += ay * ay;
    }
    int w8 = threadIdx.x >> 5;
    s_sum[w8][2 * lane] = sx;  s_sum[w8][2 * lane + 1] = sy;
    s_sq [w8][2 * lane] = qx;  s_sq [w8][2 * lane + 1] = qy;
    __syncthreads();
    if (threadIdx.x < 64) {
        float t = 0.f, tq = 0.f;
#pragma unroll
        for (int w = 0; w < 8; w++) { t += s_sum[w][threadIdx.x]; tq += s_sq[w][threadIdx.x]; }
        atomicAdd(&g_colsum[threadIdx.x * 32], t);
        atomicAdd(&g_colsq[threadIdx.x * 32], tq);
    }
    if (threadIdx.x == 0) {
        __threadfence();
        int t = atomicAdd(&g_ticket, 1);
        s_last = (t == (int)gridDim.x - 1);
    }
    __syncthreads();
    if (s_last) {
        __threadfence();
        if (threadIdx.x < 64) {
            int c = threadIdx.x;
            float s = g_colsum[c * 32], q = g_colsq[c * 32];
            const float invN = 1.f / (float)NN;
            float mean = s * invN;
            float var  = q * invN - mean * mean;
            float a    = gamma[c] * rsqrtf(var + 1e-5f);
            g_scaleA[c] = a;
            g_shiftB[c] = beta[c] - mean * a;
            g_colsum[c * 32] = 0.f;      // re-arm stats for next layer
            g_colsq[c * 32]  = 0.f;
        }
        if (threadIdx.x == 0) g_ticket = 0;
    }
}

__global__ void k_out(float* __restrict__ out) {
    int i = blockIdx.x * blockDim.x + threadIdx.x;
    if (i < NN * DD) {
        int c = i & 63;
        out[i] = fmaxf(fmaf(g_agg[i], g_scaleA[c], g_shiftB[c]), 0.f);
    }
}

// ---------------- launch ----------------
extern "C" void kernel_launch(void* const* d_in, const int* in_sizes, int n_in,
                              void* d_out, int out_size) {
    const float* x   = (const float*)d_in[0];
    const void*  ei  = d_in[1];
    const float* Ws  = (const float*)d_in[2];
    const float* bs  = (const float*)d_in[3];
    const float* gms = (const float*)d_in[4];
    const float* bts = (const float*)d_in[5];

    cudaFuncSetAttribute(k_gemm, cudaFuncAttributeMaxDynamicSharedMemorySize, GEMM_SMEM);

    k_zero_detect<<<(NN + 255) / 256, 256>>>((const int*)ei);            // 1
    k_degree<<<(NE / 2 + 255) / 256, 256>>>(ei);                         // 2
    k_scan1<<<NB_SCAN, 1024>>>();                                        // 3
    k_gemm<<<(NN + GROWS - 1) / GROWS, 256, GEMM_SMEM>>>(x, Ws, 0);      // 4 <- profiled slot
    k_fill<<<(NE + 255) / 256, 256>>>(ei);                               // 5
    k_agg<<<AGG_BLOCKS, 256>>>(bs, gms, bts);                            // 6
    for (int l = 1; l < 4; l++) {
        k_gemm<<<(NN + GROWS - 1) / GROWS, 256, GEMM_SMEM>>>(x, Ws + l * DD * DD, l);
        k_agg<<<AGG_BLOCKS, 256>>>(bs + l * DD, gms + l * DD, bts + l * DD);
    }
    k_out<<<(NN * DD + 255) / 256, 256>>>((float*)d_out);
}

// round 12
// speedup vs baseline: 1.2709x; 1.2709x over previous
#include <cuda_runtime.h>
#include <cuda_fp16.h>

#define NN 100000
#define NE 1250000
#define DD 64
#define NB_SCAN 98      // ceil(NN/1024)
#define GROWS 128       // rows per GEMM block
#define ISTR 66         // Ism row stride (floats), even for LDS.64 pairs
#define WPSTR 160       // Wp kp-row stride (floats): 8 chunks * 20
#define GEMM_SMEM ((32 * WPSTR + GROWS * ISTR) * 4)
#define AGG_BLOCKS 1184 // 8 blocks * 148 SMs = one full wave

typedef unsigned long long ull;

// ---------------- scratch (static device globals; no allocation) ----------------
__device__ int     g_is64;
__device__ int     g_ticket;
__device__ int     g_count[NN];
__device__ int     g_wcount[NN];
__device__ int     g_rowptr[NN];         // block-local exclusive prefix
__device__ int     g_bsum[128];
__device__ int     g_boff[128];          // per-1024-block offsets
__device__ float   g_dinv[NN];
__device__ int2    g_csr[NE];            // {src, weight-as-int}
__device__ __half2 g_hwh[NN * 32];       // h @ W in fp16 (gather table, 128 B/row)
__device__ float   g_agg[NN * DD];       // aggregated (pre-BN), fp32
__device__ float   g_colsum[DD * 32];    // 128B-strided slots
__device__ float   g_colsq[DD * 32];
__device__ float   g_scaleA[DD];
__device__ float   g_shiftB[DD];

// ---------------- f32x2 helpers ----------------
__device__ __forceinline__ ull ffma2(ull a, ull b, ull c) {
    ull d;
    asm("fma.rn.f32x2 %0, %1, %2, %3;" : "=l"(d) : "l"(a), "l"(b), "l"(c));
    return d;
}

// ---------------- setup ----------------
__global__ void k_zero_detect(const int* __restrict__ ei) {
    int i = blockIdx.x * blockDim.x + threadIdx.x;
    if (i < NN) { g_count[i] = 0; g_wcount[i] = 0; }
    if (blockIdx.x == 0) {
        if (threadIdx.x < 64) { g_colsum[threadIdx.x * 32] = 0.f; g_colsq[threadIdx.x * 32] = 0.f; }
        __shared__ int cnt;
        if (threadIdx.x == 0) cnt = 0;
        __syncthreads();
        int nz = 0;
#pragma unroll
        for (int j = 0; j < 8; j++) {
            int pos = 2 * (threadIdx.x + j * 256) + 1;
            if (ei[pos] != 0) nz = 1;
        }
        if (nz) atomicAdd(&cnt, 1);
        __syncthreads();
        if (threadIdx.x == 0) g_is64 = (cnt == 0) ? 1 : 0;
    }
}

__device__ __forceinline__ int load_idx(const void* ei, long long pos) {
    if (g_is64) return (int)((const long long*)ei)[pos];
    return ((const int*)ei)[pos];
}

__global__ void k_degree(const void* __restrict__ ei) {
    int t = blockIdx.x * blockDim.x + threadIdx.x;
    int e0 = 2 * t;
    if (e0 >= NE) return;
    int d0, d1 = -1;
    if (g_is64) {
        const longlong2* p = (const longlong2*)((const long long*)ei + NE + e0);
        longlong2 v = (e0 + 1 < NE) ? *p : make_longlong2(((const long long*)ei)[NE + e0], -1);
        d0 = (int)v.x; d1 = (int)v.y;
    } else {
        const int* p = (const int*)ei + NE + e0;
        d0 = p[0]; d1 = (e0 + 1 < NE) ? p[1] : -1;
    }
    if ((unsigned)d0 < NN) atomicAdd(&g_count[d0], 1);
    if ((unsigned)d1 < NN) atomicAdd(&g_count[d1], 1);
}

// block-local scan + dinv; last block (ticket) scans the 98 block sums -> g_boff
__global__ void k_scan1() {
    __shared__ int sm[1024];
    __shared__ int s_last;
    int tid = threadIdx.x;
    int i = blockIdx.x * 1024 + tid;
    int v = (i < NN) ? g_count[i] : 0;
    if (i < NN) g_dinv[i] = rsqrtf((float)(v + 1));  // +1 self loop
    sm[tid] = v;
    for (int off = 1; off < 1024; off <<= 1) {
        __syncthreads();
        int t = (tid >= off) ? sm[tid - off] : 0;
        __syncthreads();
        sm[tid] += t;
    }
    if (i < NN) g_rowptr[i] = sm[tid] - v;
    if (tid == 1023) g_bsum[blockIdx.x] = sm[1023];
    if (tid == 0) {
        __threadfence();
        int t = atomicAdd(&g_ticket, 1);
        s_last = (t == NB_SCAN - 1);
    }
    __syncthreads();
    if (s_last) {
        __threadfence();
        int v2 = (tid < NB_SCAN) ? g_bsum[tid] : 0;
        sm[tid] = (tid < 128) ? v2 : 0;
        for (int off = 1; off < 128; off <<= 1) {
            __syncthreads();
            int t = (tid >= off && tid < 128) ? sm[tid - off] : 0;
            __syncthreads();
            if (tid < 128) sm[tid] += t;
        }
        if (tid < 128) g_boff[tid] = sm[tid] - v2;
        if (tid == 0) g_ticket = 0;
    }
}

__global__ void k_fill(const void* __restrict__ ei) {
    int e = blockIdx.x * blockDim.x + threadIdx.x;
    if (e >= NE) return;
    int s = load_idx(ei, e);
    int d = load_idx(ei, (long long)NE + e);
    if ((unsigned)s >= NN || (unsigned)d >= NN) return;
    float w = g_dinv[s] * g_dinv[d];
    int p = g_rowptr[d] + g_boff[d >> 10] + atomicAdd(&g_wcount[d], 1);
    if ((unsigned)p < NE) g_csr[p] = make_int2(s, __float_as_int(w));
}

// ---------------- per-layer GEMM: hwh = fp16( BN_prev(h) @ W ) ----------------
// K packed into f32x2 lanes: acc = {sum over even k, sum over odd k}; final horizontal add.
// 128 rows x 64 cols per block; 256 thr; r4c8; rows = ty + 32*rr.
__global__ __launch_bounds__(256, 2) void k_gemm(const float* __restrict__ x,
                                                 const float* __restrict__ W, int layer) {
    extern __shared__ float smdyn[];
    float* Wp  = smdyn;                   // 32 kp-rows * WPSTR
    float* Ism = smdyn + 32 * WPSTR;      // GROWS * ISTR
    __shared__ float As[DD], Bs[DD];
    int tid = threadIdx.x;
    const float* gin = (layer == 0) ? x : g_agg;
    int bn = (layer > 0);
    if (bn && tid < 64) { As[tid] = g_scaleA[tid]; Bs[tid] = g_shiftB[tid]; }

    // stage Wp: thread tid -> (kp = tid>>3, tx = tid&7); chunk tx at kp*WPSTR + tx*20,
    // 16 floats = interleaved pairs {W[2kp][c], W[2kp+1][c]} for c = tx*8..+8.
    {
        int kp = tid >> 3, txs = tid & 7;
        const float4* W4 = (const float4*)W;
        float4 a0 = W4[(2 * kp) * 16 + txs * 2];
        float4 a1 = W4[(2 * kp) * 16 + txs * 2 + 1];
        float4 b0 = W4[(2 * kp + 1) * 16 + txs * 2];
        float4 b1 = W4[(2 * kp + 1) * 16 + txs * 2 + 1];
        float4* wp = (float4*)&Wp[kp * WPSTR + txs * 20];
        wp[0] = make_float4(a0.x, b0.x, a0.y, b0.y);
        wp[1] = make_float4(a0.z, b0.z, a0.w, b0.w);
        wp[2] = make_float4(a1.x, b1.x, a1.y, b1.y);
        wp[3] = make_float4(a1.z, b1.z, a1.w, b1.w);
    }
    __syncthreads();   // As/Bs ready too

    int row0 = blockIdx.x * GROWS;
#pragma unroll
    for (int i = 0; i < 8; i++) {
        int idx4 = tid + i * 256;
        int r = idx4 >> 4, c4 = (idx4 & 15) * 4;
        int gr = row0 + r;
        float4 v = {0.f, 0.f, 0.f, 0.f};
        if (gr < NN) {
            v = *(const float4*)&gin[gr * DD + c4];
            if (bn) {
                v.x = fmaxf(fmaf(v.x, As[c4 + 0], Bs[c4 + 0]), 0.f);
                v.y = fmaxf(fmaf(v.y, As[c4 + 1], Bs[c4 + 1]), 0.f);
                v.z = fmaxf(fmaf(v.z, As[c4 + 2], Bs[c4 + 2]), 0.f);
                v.w = fmaxf(fmaf(v.w, As[c4 + 3], Bs[c4 + 3]), 0.f);
            }
        }
        float* ip = &Ism[r * ISTR + c4];
        ip[0] = v.x; ip[1] = v.y; ip[2] = v.z; ip[3] = v.w;
    }
    __syncthreads();

    int tx = tid & 7, ty = tid >> 3;      // ty 0..31 -> rows ty + 32*rr
    ull acc[4][8];
#pragma unroll
    for (int r = 0; r < 4; r++)
#pragma unroll
        for (int c = 0; c < 8; c++) acc[r][c] = 0ull;

#pragma unroll 8
    for (int kp = 0; kp < 32; kp++) {
        ull a0 = *(const ull*)&Ism[(ty      ) * ISTR + 2 * kp];
        ull a1 = *(const ull*)&Ism[(ty + 32 ) * ISTR + 2 * kp];
        ull a2 = *(const ull*)&Ism[(ty + 64 ) * ISTR + 2 * kp];
        ull a3 = *(const ull*)&Ism[(ty + 96 ) * ISTR + 2 * kp];
        const ull* wp = (const ull*)&Wp[kp * WPSTR + tx * 20];
        ull w0 = wp[0], w1 = wp[1], w2 = wp[2], w3 = wp[3];
        ull w4 = wp[4], w5 = wp[5], w6 = wp[6], w7 = wp[7];
        acc[0][0] = ffma2(a0, w0, acc[0][0]); acc[0][1] = ffma2(a0, w1, acc[0][1]);
        acc[0][2] = ffma2(a0, w2, acc[0][2]); acc[0][3] = ffma2(a0, w3, acc[0][3]);
        acc[0][4] = ffma2(a0, w4, acc[0][4]); acc[0][5] = ffma2(a0, w5, acc[0][5]);
        acc[0][6] = ffma2(a0, w6, acc[0][6]); acc[0][7] = ffma2(a0, w7, acc[0][7]);
        acc[1][0] = ffma2(a1, w0, acc[1][0]); acc[1][1] = ffma2(a1, w1, acc[1][1]);
        acc[1][2] = ffma2(a1, w2, acc[1][2]); acc[1][3] = ffma2(a1, w3, acc[1][3]);
        acc[1][4] = ffma2(a1, w4, acc[1][4]); acc[1][5] = ffma2(a1, w5, acc[1][5]);
        acc[1][6] = ffma2(a1, w6, acc[1][6]); acc[1][7] = ffma2(a1, w7, acc[1][7]);
        acc[2][0] = ffma2(a2, w0, acc[2][0]); acc[2][1] = ffma2(a2, w1, acc[2][1]);
        acc[2][2] = ffma2(a2, w2, acc[2][2]); acc[2][3] = ffma2(a2, w3, acc[2][3]);
        acc[2][4] = ffma2(a2, w4, acc[2][4]); acc[2][5] = ffma2(a2, w5, acc[2][5]);
        acc[2][6] = ffma2(a2, w6, acc[2][6]); acc[2][7] = ffma2(a2, w7, acc[2][7]);
        acc[3][0] = ffma2(a3, w0, acc[3][0]); acc[3][1] = ffma2(a3, w1, acc[3][1]);
        acc[3][2] = ffma2(a3, w2, acc[3][2]); acc[3][3] = ffma2(a3, w3, acc[3][3]);
        acc[3][4] = ffma2(a3, w4, acc[3][4]); acc[3][5] = ffma2(a3, w5, acc[3][5]);
        acc[3][6] = ffma2(a3, w6, acc[3][6]); acc[3][7] = ffma2(a3, w7, acc[3][7]);
    }
#pragma unroll
    for (int rr = 0; rr < 4; rr++) {
        int gr = row0 + ty + 32 * rr;
        if (gr < NN) {
            float o[8];
#pragma unroll
            for (int c = 0; c < 8; c++) {
                float ax, ay;
                asm("mov.b64 {%0, %1}, %2;" : "=f"(ax), "=f"(ay) : "l"(acc[rr][c]));
                o[c] = ax + ay;        // even-k sum + odd-k sum
            }
            __half2 h4[4];
#pragma unroll
            for (int j = 0; j < 4; j++) h4[j] = __floats2half2_rn(o[2 * j], o[2 * j + 1]);
            *(uint2*)&g_hwh[gr * 32 + tx * 4]     = *(uint2*)&h4[0];
            *(uint2*)&g_hwh[gr * 32 + tx * 4 + 2] = *(uint2*)&h4[2];
        }
    }
}

// ---------------- aggregation (1 node/warp, 4-unrolled) + BN stats + finalize ----------------
__device__ __forceinline__ int rp(int n) { return g_rowptr[n] + g_boff[n >> 10]; }

__global__ __launch_bounds__(256) void k_agg(const float* __restrict__ bias,
                                             const float* __restrict__ gamma,
                                             const float* __restrict__ beta) {
    __shared__ float s_sum[8][64];
    __shared__ float s_sq[8][64];
    __shared__ int s_last;
    int lane = threadIdx.x & 31;
    int gw = (blockIdx.x * blockDim.x + threadIdx.x) >> 5;
    int nw = (gridDim.x * 256) >> 5;
    float bx = bias[2 * lane], by = bias[2 * lane + 1];
    float sx = 0.f, sy = 0.f, qx = 0.f, qy = 0.f;
    for (int n = gw; n < NN; n += nw) {
        int p = rp(n);
        int p1 = (n + 1 == NN) ? NE : rp(n + 1);
        float ax = 0.f, ay = 0.f;
#pragma unroll 1
        for (; p + 4 <= p1; p += 4) {
            int2 e0 = g_csr[p];
            int2 e1 = g_csr[p + 1];
            int2 e2 = g_csr[p + 2];
            int2 e3 = g_csr[p + 3];
            float2 v0 = __half22float2(g_hwh[e0.x * 32 + lane]);
            float2 v1 = __half22float2(g_hwh[e1.x * 32 + lane]);
            float2 v2 = __half22float2(g_hwh[e2.x * 32 + lane]);
            float2 v3 = __half22float2(g_hwh[e3.x * 32 + lane]);
            float w0 = __int_as_float(e0.y), w1 = __int_as_float(e1.y);
            float w2 = __int_as_float(e2.y), w3 = __int_as_float(e3.y);
            ax = fmaf(v0.x, w0, ax); ay = fmaf(v0.y, w0, ay);
            ax = fmaf(v1.x, w1, ax); ay = fmaf(v1.y, w1, ay);
            ax = fmaf(v2.x, w2, ax); ay = fmaf(v2.y, w2, ay);
            ax = fmaf(v3.x, w3, ax); ay = fmaf(v3.y, w3, ay);
        }
#pragma unroll 1
        for (; p < p1; p++) {
            int2 e = g_csr[p];
            float w = __int_as_float(e.y);
            float2 v = __half22float2(g_hwh[e.x * 32 + lane]);
            ax = fmaf(v.x, w, ax); ay = fmaf(v.y, w, ay);
        }
        float di = g_dinv[n];
        float sw = di * di;
        float2 sv = __half22float2(g_hwh[n * 32 + lane]);
        ax = fmaf(sv.x, sw, ax) + bx;
        ay = fmaf(sv.y, sw, ay) + by;
        *(float2*)&g_agg[n * DD + 2 * lane] = make_float2(ax, ay);
        sx += ax; sy += ay; qx += ax * ax; qy += ay * ay;
    }
    int w8 = threadIdx.x >> 5;
    s_sum[w8][2 * lane] = sx;  s_sum[w8][2 * lane + 1] = sy;
    s_sq [w8][2 * lane] = qx;  s_sq [w8][2 * lane + 1] = qy;
    __syncthreads();
    if (threadIdx.x < 64) {
        float t = 0.f, tq = 0.f;
#pragma unroll
        for (int w = 0; w < 8; w++) { t += s_sum[w][threadIdx.x]; tq += s_sq[w][threadIdx.x]; }
        atomicAdd(&g_colsum[threadIdx.x * 32], t);
        atomicAdd(&g_colsq[threadIdx.x * 32], tq);
    }
    if (threadIdx.x == 0) {
        __threadfence();
        int t = atomicAdd(&g_ticket, 1);
        s_last = (t == (int)gridDim.x - 1);
    }
    __syncthreads();
    if (s_last) {
        __threadfence();
        if (threadIdx.x < 64) {
            int c = threadIdx.x;
            float s = g_colsum[c * 32], q = g_colsq[c * 32];
            const float invN = 1.f / (float)NN;
            float mean = s * invN;
            float var  = q * invN - mean * mean;
            float a    = gamma[c] * rsqrtf(var + 1e-5f);
            g_scaleA[c] = a;
            g_shiftB[c] = beta[c] - mean * a;
            g_colsum[c * 32] = 0.f;      // re-arm stats for next layer
            g_colsq[c * 32]  = 0.f;
        }
        if (threadIdx.x == 0) g_ticket = 0;
    }
}

__global__ void k_out(float* __restrict__ out) {
    int i = blockIdx.x * blockDim.x + threadIdx.x;
    if (i < NN * DD) {
        int c = i & 63;
        out[i] = fmaxf(fmaf(g_agg[i], g_scaleA[c], g_shiftB[c]), 0.f);
    }
}

// ---------------- launch ----------------
extern "C" void kernel_launch(void* const* d_in, const int* in_sizes, int n_in,
                              void* d_out, int out_size) {
    const float* x   = (const float*)d_in[0];
    const void*  ei  = d_in[1];
    const float* Ws  = (const float*)d_in[2];
    const float* bs  = (const float*)d_in[3];
    const float* gms = (const float*)d_in[4];
    const float* bts = (const float*)d_in[5];

    cudaFuncSetAttribute(k_gemm, cudaFuncAttributeMaxDynamicSharedMemorySize, GEMM_SMEM);

    k_zero_detect<<<(NN + 255) / 256, 256>>>((const int*)ei);            // 1
    k_degree<<<(NE / 2 + 255) / 256, 256>>>(ei);                         // 2
    k_scan1<<<NB_SCAN, 1024>>>();                                        // 3
    k_gemm<<<(NN + GROWS - 1) / GROWS, 256, GEMM_SMEM>>>(x, Ws, 0);      // 4 <- profiled slot
    k_fill<<<(NE + 255) / 256, 256>>>(ei);                               // 5
    k_agg<<<AGG_BLOCKS, 256>>>(bs, gms, bts);                            // 6
    for (int l = 1; l < 4; l++) {
        k_gemm<<<(NN + GROWS - 1) / GROWS, 256, GEMM_SMEM>>>(x, Ws + l * DD * DD, l);
        k_agg<<<AGG_BLOCKS, 256>>>(bs + l * DD, gms + l * DD, bts + l * DD);
    }
    k_out<<<(NN * DD + 255) / 256, 256>>>((float*)d_out);
}